// round 2
// baseline (speedup 1.0000x reference)
#include <cuda_runtime.h>
#include <math.h>

// B=8, S=8192, D=1024, G=512 groups of GS=16, K=64 selected, H=16, HD=64, DH4=256

// ---------------- scratch ----------------
__device__ float g_scoresP[2 * 4096];   // partial scores per n-half
__device__ int   g_topidx[8 * 64];
__device__ float g_sel[512 * 1024];
__device__ float g_q[512 * 1024];
__device__ float g_k[512 * 1024];
__device__ float g_v[512 * 1024];
__device__ float g_ctx[512 * 1024];

// ============ 1) scorer with fused mean-pool ============
// scores_part = relu(mean16(hidden) @ Ws1 + bs1) @ Ws2, N split in 2 halves.
// grid (2, 128): x = n-half (L2-pairs adjacent), y = 32-group row block.
// 128 threads: tx=tid&15 (TN=8 cols), ty=tid>>4 (TM=4 rows).
__global__ __launch_bounds__(128) void scorer_kernel(const float* __restrict__ hid,
                                                     const float* __restrict__ Ws1,
                                                     const float* __restrict__ bs1,
                                                     const float* __restrict__ Ws2) {
    __shared__ float As[16 * 36];
    __shared__ float Bs[16 * 128];
    __shared__ float red[32 * 17];
    int tid = threadIdx.x;
    int nb = blockIdx.x;
    int rowBase = blockIdx.y * 32;
    int tx = tid & 15, ty = tid >> 4;
    int nBase = nb * 128;
    float acc[4][8];
#pragma unroll
    for (int i = 0; i < 4; i++)
#pragma unroll
        for (int j = 0; j < 8; j++) acc[i][j] = 0.f;

    const float4* H4 = (const float4*)hid;
    int mA = tid >> 2, c4A = tid & 3;
    int aBase = (rowBase + mA) * 16 * 256 + c4A;

    for (int kt4 = 0; kt4 < 256; kt4 += 4) {
        // A tile: mean-pool 16 hidden rows on the fly
        float4 s = make_float4(0.f, 0.f, 0.f, 0.f);
#pragma unroll
        for (int r = 0; r < 16; r++) {
            float4 v = H4[aBase + kt4 + r * 256];
            s.x += v.x; s.y += v.y; s.z += v.z; s.w += v.w;
        }
        const float inv = 1.0f / 16.0f;
        As[(c4A * 4 + 0) * 36 + mA] = s.x * inv;
        As[(c4A * 4 + 1) * 36 + mA] = s.y * inv;
        As[(c4A * 4 + 2) * 36 + mA] = s.z * inv;
        As[(c4A * 4 + 3) * 36 + mA] = s.w * inv;
        // B tile
#pragma unroll
        for (int i = 0; i < 4; i++) {
            int e = tid + 128 * i;
            int row = e >> 5, c4 = e & 31;
            *(float4*)&Bs[row * 128 + c4 * 4] =
                *(const float4*)&Ws1[(kt4 * 4 + row) * 256 + nBase + c4 * 4];
        }
        __syncthreads();
#pragma unroll
        for (int k = 0; k < 16; k++) {
            float4 a = *(float4*)&As[k * 36 + ty * 4];
            float4 b0 = *(float4*)&Bs[k * 128 + tx * 8];
            float4 b1 = *(float4*)&Bs[k * 128 + tx * 8 + 4];
            float av[4] = {a.x, a.y, a.z, a.w};
            float bv[8] = {b0.x, b0.y, b0.z, b0.w, b1.x, b1.y, b1.z, b1.w};
#pragma unroll
            for (int i = 0; i < 4; i++)
#pragma unroll
                for (int j = 0; j < 8; j++) acc[i][j] = fmaf(av[i], bv[j], acc[i][j]);
        }
        __syncthreads();
    }
    // epilogue: relu + bias + contract with Ws2 (partial over this n-half)
    float part[4] = {0.f, 0.f, 0.f, 0.f};
#pragma unroll
    for (int j = 0; j < 8; j++) {
        int col = nBase + tx * 8 + j;
        float w2 = Ws2[col];
        float b1v = bs1[col];
#pragma unroll
        for (int i = 0; i < 4; i++) {
            float v = fmaxf(acc[i][j] + b1v, 0.f);
            part[i] = fmaf(v, w2, part[i]);
        }
    }
#pragma unroll
    for (int i = 0; i < 4; i++) red[(ty * 4 + i) * 17 + tx] = part[i];
    __syncthreads();
    if (tid < 32) {
        float sres = 0.f;
#pragma unroll
        for (int x = 0; x < 16; x++) sres += red[tid * 17 + x];
        g_scoresP[nb * 4096 + rowBase + tid] = sres;
    }
}

// ============ 2) top-64 via bitonic sort (softmax+bs2 skipped: monotonic) ============
__global__ __launch_bounds__(256) void topk_kernel() {
    int b = blockIdx.x, t = threadIdx.x;
    __shared__ float v[512];
    __shared__ int ix[512];
    for (int e = t; e < 512; e += 256) {
        v[e] = g_scoresP[b * 512 + e] + g_scoresP[4096 + b * 512 + e];
        ix[e] = e;
    }
    __syncthreads();
    for (int k = 2; k <= 512; k <<= 1) {
        for (int j = k >> 1; j > 0; j >>= 1) {
#pragma unroll
            for (int base = 0; base < 2; base++) {
                int i = t + base * 256;
                int ixj = i ^ j;
                if (ixj > i) {
                    bool dir = (i & k) == 0;  // descending overall
                    float vi = v[i], vj = v[ixj];
                    if ((vi < vj) == dir) {
                        v[i] = vj; v[ixj] = vi;
                        int tmp = ix[i]; ix[i] = ix[ixj]; ix[ixj] = tmp;
                    }
                }
            }
            __syncthreads();
        }
    }
    if (t < 64) g_topidx[b * 64 + t] = ix[t];
}

// ============ 3) gather: recompute means of the 64 selected groups ============
__global__ __launch_bounds__(256) void gather_kernel(const float* __restrict__ hid) {
    int r = blockIdx.x;        // b*64 + kk
    int b = r >> 6;
    int idx = g_topidx[r];
    int t = threadIdx.x;
    const float4* H4 = (const float4*)hid;
    float4* S4 = (float4*)g_sel;
    int base = (b * 512 + idx) * 16 * 256 + t;
    float4 s = make_float4(0.f, 0.f, 0.f, 0.f);
#pragma unroll
    for (int rr = 0; rr < 16; rr++) {
        float4 vv = H4[base + rr * 256];
        s.x += vv.x; s.y += vv.y; s.z += vv.z; s.w += vv.w;
    }
    const float inv = 1.0f / 16.0f;
    s.x *= inv; s.y *= inv; s.z *= inv; s.w *= inv;
    S4[r * 256 + t] = s;
}

// ============ 4) QKV GEMM (+ zero-fill of output, free under compute) ============
// M=512, N=1024, K=1024. BM=64, BN=64, BK=16, TM=4, TN=8, 128 threads.
// grid (8, 16, 3): z selects Wq/Wk/Wv -> g_q/g_k/g_v.
__global__ __launch_bounds__(128) void qkv_kernel(const float* __restrict__ Wq,
                                                  const float* __restrict__ Wk,
                                                  const float* __restrict__ Wv,
                                                  float* __restrict__ out) {
    int tid = threadIdx.x;
    // zero-fill the 256MB output with streaming stores (overlaps GEMM compute)
    {
        int lin = blockIdx.x + blockIdx.y * 8 + blockIdx.z * 128;
        float4 z = make_float4(0.f, 0.f, 0.f, 0.f);
        float4* o4 = (float4*)out;
        for (int i = lin * 128 + tid; i < 16777216; i += 49152) __stcs(o4 + i, z);
    }
    const float* Bm = (blockIdx.z == 0) ? Wq : ((blockIdx.z == 1) ? Wk : Wv);
    float* Cm = (blockIdx.z == 0) ? g_q : ((blockIdx.z == 1) ? g_k : g_v);

    __shared__ float As[16 * 68];
    __shared__ float Bs[16 * 64];
    int tx = tid & 7, ty = tid >> 3;  // tx: 8 cols of TN=8, ty: 16 rows of TM=4
    int rowBase = blockIdx.x * 64, colBase = blockIdx.y * 64;
    float acc[4][8];
#pragma unroll
    for (int i = 0; i < 4; i++)
#pragma unroll
        for (int j = 0; j < 8; j++) acc[i][j] = 0.f;

    const float4* A4 = (const float4*)g_sel;
    for (int kt4 = 0; kt4 < 256; kt4 += 4) {
#pragma unroll
        for (int i = 0; i < 2; i++) {
            int e = tid + 128 * i;
            int m = e >> 2, c4 = e & 3;
            float4 a = A4[(rowBase + m) * 256 + kt4 + c4];
            As[(c4 * 4 + 0) * 68 + m] = a.x;
            As[(c4 * 4 + 1) * 68 + m] = a.y;
            As[(c4 * 4 + 2) * 68 + m] = a.z;
            As[(c4 * 4 + 3) * 68 + m] = a.w;
        }
#pragma unroll
        for (int i = 0; i < 2; i++) {
            int e = tid + 128 * i;
            int row = e >> 4, c4 = e & 15;
            *(float4*)&Bs[row * 64 + c4 * 4] =
                *(const float4*)&Bm[(kt4 * 4 + row) * 1024 + colBase + c4 * 4];
        }
        __syncthreads();
#pragma unroll
        for (int k = 0; k < 16; k++) {
            float4 a = *(float4*)&As[k * 68 + ty * 4];
            float4 b0 = *(float4*)&Bs[k * 64 + tx * 8];
            float4 b1 = *(float4*)&Bs[k * 64 + tx * 8 + 4];
            float av[4] = {a.x, a.y, a.z, a.w};
            float bv[8] = {b0.x, b0.y, b0.z, b0.w, b1.x, b1.y, b1.z, b1.w};
#pragma unroll
            for (int i = 0; i < 4; i++)
#pragma unroll
                for (int j = 0; j < 8; j++) acc[i][j] = fmaf(av[i], bv[j], acc[i][j]);
        }
        __syncthreads();
    }
#pragma unroll
    for (int i = 0; i < 4; i++) {
        int row = rowBase + ty * 4 + i;
        *(float4*)&Cm[row * 1024 + colBase + tx * 8] =
            make_float4(acc[i][0], acc[i][1], acc[i][2], acc[i][3]);
        *(float4*)&Cm[row * 1024 + colBase + tx * 8 + 4] =
            make_float4(acc[i][4], acc[i][5], acc[i][6], acc[i][7]);
    }
}

// ============ 5) attention: warp-per-query ============
// grid (8, 16, 8): x = query-group of 8, y = head, z = batch. 256 threads = 8 warps.
__global__ __launch_bounds__(256) void attn_kernel() {
    __shared__ float Ks[64 * 65];
    __shared__ float Vs[64 * 65];
    __shared__ float Qs[8 * 64];
    __shared__ float Ps[8 * 64];
    int t = threadIdx.x;
    int qBase = blockIdx.x * 8;
    int h = blockIdx.y, b = blockIdx.z;
    const float4* K4 = (const float4*)g_k;
    const float4* V4 = (const float4*)g_v;
    const float4* Q4 = (const float4*)g_q;
#pragma unroll
    for (int i = 0; i < 4; i++) {
        int e = t + 256 * i;
        int j = e >> 4, c4 = e & 15;
        float4 kv = K4[(b * 64 + j) * 256 + h * 16 + c4];
        int s = j * 65 + c4 * 4;
        Ks[s] = kv.x; Ks[s + 1] = kv.y; Ks[s + 2] = kv.z; Ks[s + 3] = kv.w;
        float4 vv = V4[(b * 64 + j) * 256 + h * 16 + c4];
        Vs[s] = vv.x; Vs[s + 1] = vv.y; Vs[s + 2] = vv.z; Vs[s + 3] = vv.w;
    }
    if (t < 128) {
        int q = t >> 4, c4 = t & 15;
        float4 qv = Q4[(b * 64 + qBase + q) * 256 + h * 16 + c4];
        Qs[q * 64 + c4 * 4] = qv.x; Qs[q * 64 + c4 * 4 + 1] = qv.y;
        Qs[q * 64 + c4 * 4 + 2] = qv.z; Qs[q * 64 + c4 * 4 + 3] = qv.w;
    }
    __syncthreads();
    int w = t >> 5, lane = t & 31;
    int j0 = lane, j1 = lane + 32;
    float s0 = 0.f, s1 = 0.f;
#pragma unroll
    for (int d = 0; d < 64; d++) {
        float qd = Qs[w * 64 + d];
        s0 = fmaf(qd, Ks[j0 * 65 + d], s0);
        s1 = fmaf(qd, Ks[j1 * 65 + d], s1);
    }
    s0 *= 0.125f; s1 *= 0.125f;
    float m = fmaxf(s0, s1);
#pragma unroll
    for (int off = 16; off > 0; off >>= 1) m = fmaxf(m, __shfl_xor_sync(0xffffffffu, m, off));
    float e0 = __expf(s0 - m), e1 = __expf(s1 - m);
    float l = e0 + e1;
#pragma unroll
    for (int off = 16; off > 0; off >>= 1) l += __shfl_xor_sync(0xffffffffu, l, off);
    float inv = 1.f / l;
    Ps[w * 64 + j0] = e0 * inv;
    Ps[w * 64 + j1] = e1 * inv;
    __syncwarp();
    int d0 = lane, d1 = lane + 32;
    float a0 = 0.f, a1 = 0.f;
#pragma unroll
    for (int j = 0; j < 64; j++) {
        float p = Ps[w * 64 + j];
        a0 = fmaf(p, Vs[j * 65 + d0], a0);
        a1 = fmaf(p, Vs[j * 65 + d1], a1);
    }
    int row = b * 64 + qBase + w;
    g_ctx[row * 1024 + h * 64 + d0] = a0;
    g_ctx[row * 1024 + h * 64 + d1] = a1;
}

// ============ 6) out-proj GEMM with fused scatter-broadcast ============
// C = g_ctx @ Wo, each output row broadcast to its 16 sequence positions.
__global__ __launch_bounds__(128) void proj_kernel(const float* __restrict__ Wo,
                                                   float* __restrict__ out) {
    __shared__ float As[16 * 68];
    __shared__ float Bs[16 * 64];
    int tid = threadIdx.x;
    int tx = tid & 7, ty = tid >> 3;
    int rowBase = blockIdx.x * 64, colBase = blockIdx.y * 64;
    float acc[4][8];
#pragma unroll
    for (int i = 0; i < 4; i++)
#pragma unroll
        for (int j = 0; j < 8; j++) acc[i][j] = 0.f;

    const float4* A4 = (const float4*)g_ctx;
    for (int kt4 = 0; kt4 < 256; kt4 += 4) {
#pragma unroll
        for (int i = 0; i < 2; i++) {
            int e = tid + 128 * i;
            int m = e >> 2, c4 = e & 3;
            float4 a = A4[(rowBase + m) * 256 + kt4 + c4];
            As[(c4 * 4 + 0) * 68 + m] = a.x;
            As[(c4 * 4 + 1) * 68 + m] = a.y;
            As[(c4 * 4 + 2) * 68 + m] = a.z;
            As[(c4 * 4 + 3) * 68 + m] = a.w;
        }
#pragma unroll
        for (int i = 0; i < 2; i++) {
            int e = tid + 128 * i;
            int row = e >> 4, c4 = e & 15;
            *(float4*)&Bs[row * 64 + c4 * 4] =
                *(const float4*)&Wo[(kt4 * 4 + row) * 1024 + colBase + c4 * 4];
        }
        __syncthreads();
#pragma unroll
        for (int k = 0; k < 16; k++) {
            float4 a = *(float4*)&As[k * 68 + ty * 4];
            float4 b0 = *(float4*)&Bs[k * 64 + tx * 8];
            float4 b1 = *(float4*)&Bs[k * 64 + tx * 8 + 4];
            float av[4] = {a.x, a.y, a.z, a.w};
            float bv[8] = {b0.x, b0.y, b0.z, b0.w, b1.x, b1.y, b1.z, b1.w};
#pragma unroll
            for (int i = 0; i < 4; i++)
#pragma unroll
                for (int j = 0; j < 8; j++) acc[i][j] = fmaf(av[i], bv[j], acc[i][j]);
        }
        __syncthreads();
    }
    // scatter-broadcast epilogue: row r -> 16 positions of its selected group
#pragma unroll
    for (int i = 0; i < 4; i++) {
        int r = rowBase + ty * 4 + i;
        int b = r >> 6;
        int idx = g_topidx[r];
        int base = (b * 8192 + idx * 16) * 1024 + colBase + tx * 8;
        float4 lo = make_float4(acc[i][0], acc[i][1], acc[i][2], acc[i][3]);
        float4 hi = make_float4(acc[i][4], acc[i][5], acc[i][6], acc[i][7]);
#pragma unroll
        for (int rr = 0; rr < 16; rr++) {
            *(float4*)&out[base + rr * 1024] = lo;
            *(float4*)&out[base + rr * 1024 + 4] = hi;
        }
    }
}

// ---------------- launch ----------------
extern "C" void kernel_launch(void* const* d_in, const int* in_sizes, int n_in,
                              void* d_out, int out_size) {
    const float* hid = (const float*)d_in[0];
    const float* Wq  = (const float*)d_in[1];
    const float* Wk  = (const float*)d_in[2];
    const float* Wv  = (const float*)d_in[3];
    const float* Wo  = (const float*)d_in[4];
    const float* Ws1 = (const float*)d_in[5];
    const float* bs1 = (const float*)d_in[6];
    const float* Ws2 = (const float*)d_in[7];
    float* out = (float*)d_out;

    scorer_kernel<<<dim3(2, 128), 128>>>(hid, Ws1, bs1, Ws2);
    topk_kernel<<<8, 256>>>();
    gather_kernel<<<512, 256>>>(hid);
    qkv_kernel<<<dim3(8, 16, 3), 128>>>(Wq, Wk, Wv, out);
    attn_kernel<<<dim3(8, 16, 8), 256>>>();
    proj_kernel<<<dim3(8, 16), 128>>>(Wo, out);
}